// round 10
// baseline (speedup 1.0000x reference)
#include <cuda_runtime.h>
#include <math.h>

#define N_NODES   1000000
#define K_TOP     10000
#define S_RIP     60
#define D_H       128
#define D_IN      17
#define LN_EPS    1e-5f
#define SUM_BLOCKS 512
#define TIED_CAP  4096

// -------- device scratch (no allocations allowed) --------
__device__ unsigned int g_keys[N_NODES];
__device__ unsigned int g_hist1[2048];
__device__ unsigned int g_hist2[2048];
__device__ unsigned int g_hist3[1024];
// state: [0]=b1 [1]=K1 [2]=b2 [3]=K2 [4]=T [5]=need [6]=tied_count
__device__ unsigned int g_state[8];
__device__ float        g_partials[SUM_BLOCKS * 8];
__device__ int          g_tied[TIED_CAP];
__device__ float        g_x[S_RIP * D_IN];
__device__ float        g_h[S_RIP * D_H];

// -------- pass 1: keys + level-1 histogram (bits [21:31]) --------
__global__ void k_keys_hist1(const float* __restrict__ nf) {
    __shared__ unsigned int sh[2048];
    for (int i = threadIdx.x; i < 2048; i += blockDim.x) sh[i] = 0;
    __syncthreads();
    int stride = gridDim.x * blockDim.x;
    const float4* nf4 = (const float4*)nf;   // row i starts at float 12*i -> float4 3*i
    for (int i = blockIdx.x * blockDim.x + threadIdx.x; i < N_NODES; i += stride) {
        float4 v = nf4[i * 3];               // v.x,v.y,v.z = velocity
        float s = v.x * v.x + v.y * v.y + v.z * v.z;
        unsigned int u = __float_as_uint(s); // s >= 0: uint order == float order
        g_keys[i] = u;
        atomicAdd(&sh[u >> 21], 1u);
    }
    __syncthreads();
    for (int i = threadIdx.x; i < 2048; i += blockDim.x)
        if (sh[i]) atomicAdd(&g_hist1[i], sh[i]);
}

// -------- level-2 histogram over candidate bucket (bits [10:21]) --------
__global__ void k_hist2() {
    __shared__ unsigned int sh[2048];
    for (int i = threadIdx.x; i < 2048; i += blockDim.x) sh[i] = 0;
    __syncthreads();
    unsigned int b1 = g_state[0];
    int stride = gridDim.x * blockDim.x;
    for (int i = blockIdx.x * blockDim.x + threadIdx.x; i < N_NODES; i += stride) {
        unsigned int u = g_keys[i];
        if ((u >> 21) == b1) atomicAdd(&sh[(u >> 10) & 0x7FFu], 1u);
    }
    __syncthreads();
    for (int i = threadIdx.x; i < 2048; i += blockDim.x)
        if (sh[i]) atomicAdd(&g_hist2[i], sh[i]);
}

// -------- level-3 histogram (bits [0:10]) --------
__global__ void k_hist3() {
    __shared__ unsigned int sh[1024];
    for (int i = threadIdx.x; i < 1024; i += blockDim.x) sh[i] = 0;
    __syncthreads();
    unsigned int prefix21 = (g_state[0] << 11) | g_state[2];
    int stride = gridDim.x * blockDim.x;
    for (int i = blockIdx.x * blockDim.x + threadIdx.x; i < N_NODES; i += stride) {
        unsigned int u = g_keys[i];
        if ((u >> 10) == prefix21) atomicAdd(&sh[u & 0x3FFu], 1u);
    }
    __syncthreads();
    for (int i = threadIdx.x; i < 1024; i += blockDim.x)
        if (sh[i]) atomicAdd(&g_hist3[i], sh[i]);
}

// -------- single-block scan: find bucket containing the K-th largest --------
__global__ void k_scan(int level) {
    __shared__ unsigned int csum[256];
    __shared__ unsigned int suf[256];
    const unsigned int* hist = (level == 1) ? g_hist1 : (level == 2) ? g_hist2 : g_hist3;
    int nbins = (level == 3) ? 1024 : 2048;
    unsigned int K = (level == 1) ? (unsigned int)K_TOP
                   : (level == 2) ? g_state[1] : g_state[3];
    int t = threadIdx.x;
    int chunk = nbins / 256;
    unsigned int s = 0;
    for (int b = t * chunk; b < (t + 1) * chunk; b++) s += hist[b];
    csum[t] = s;
    __syncthreads();
    if (t == 0) {
        unsigned int acc = 0;
        for (int c = 255; c >= 0; c--) { suf[c] = acc; acc += csum[c]; }
    }
    __syncthreads();
    // walk own chunk top-down; exactly one thread finds the bucket
    unsigned int cum = suf[t];
    for (int b = (t + 1) * chunk - 1; b >= t * chunk; b--) {
        unsigned int h = hist[b];
        if (cum < K && cum + h >= K) {
            unsigned int rem = K - cum;
            if (level == 1)      { g_state[0] = (unsigned int)b; g_state[1] = rem; }
            else if (level == 2) { g_state[2] = (unsigned int)b; g_state[3] = rem; }
            else {
                g_state[4] = (g_state[0] << 21) | (g_state[2] << 10) | (unsigned int)b;
                g_state[5] = rem;
            }
        }
        cum += h;
    }
}

// -------- reduction: sums over keys > T; collect ties at == T --------
__global__ void k_sum(const float* __restrict__ nf, const float* __restrict__ wp,
                      const float* __restrict__ mp) {
    unsigned int T = g_state[4];
    float acc[8];
#pragma unroll
    for (int c = 0; c < 8; c++) acc[c] = 0.f;
    int stride = gridDim.x * blockDim.x;
    for (int i = blockIdx.x * blockDim.x + threadIdx.x; i < N_NODES; i += stride) {
        unsigned int u = g_keys[i];
        if (u > T) {
            acc[0] += nf[i * 12 + 0];
            acc[1] += nf[i * 12 + 1];
            acc[2] += nf[i * 12 + 2];
            acc[3] += wp[i * 3 + 0];
            acc[4] += wp[i * 3 + 1];
            acc[5] += wp[i * 3 + 2];
            acc[6] += mp[i * 2 + 0];
            acc[7] += mp[i * 2 + 1];
        } else if (u == T) {
            int p = (int)atomicAdd(&g_state[6], 1u);
            if (p < TIED_CAP) g_tied[p] = i;
        }
    }
    __shared__ float red[256];
    for (int c = 0; c < 8; c++) {
        red[threadIdx.x] = acc[c];
        __syncthreads();
        for (int s = 128; s > 0; s >>= 1) {
            if (threadIdx.x < s) red[threadIdx.x] += red[threadIdx.x + s];
            __syncthreads();
        }
        if (threadIdx.x == 0) g_partials[blockIdx.x * 8 + c] = red[0];
        __syncthreads();
    }
}

// -------- finalize: reduce partials, ties (sorted by index), build x + LN0 --------
__global__ void k_finalize(const float* __restrict__ nf, const float* __restrict__ wp,
                           const float* __restrict__ mp, const int* __restrict__ rip,
                           const float* __restrict__ ln0s, const float* __restrict__ ln0b) {
    __shared__ float hv[8];
    int t = threadIdx.x;
    if (t < 8) {
        float a = 0.f;
        for (int b = 0; b < SUM_BLOCKS; b++) a += g_partials[b * 8 + t];
        hv[t] = a;
    }
    __syncthreads();
    if (t == 0) {
        int cnt = (int)g_state[6];
        if (cnt > TIED_CAP) cnt = TIED_CAP;
        int need = (int)g_state[5];
        // insertion sort ascending -> matches stable lowest-index tie-break
        for (int i = 1; i < cnt; i++) {
            int v = g_tied[i];
            int j = i - 1;
            while (j >= 0 && g_tied[j] > v) { g_tied[j + 1] = g_tied[j]; j--; }
            g_tied[j + 1] = v;
        }
        for (int i = 0; i < need && i < cnt; i++) {
            int idx = g_tied[i];
            hv[0] += nf[idx * 12 + 0];
            hv[1] += nf[idx * 12 + 1];
            hv[2] += nf[idx * 12 + 2];
            hv[3] += wp[idx * 3 + 0];
            hv[4] += wp[idx * 3 + 1];
            hv[5] += wp[idx * 3 + 2];
            hv[6] += mp[idx * 2 + 0];
            hv[7] += mp[idx * 2 + 1];
        }
    }
    __syncthreads();
    if (t < S_RIP) {
        int r = rip[t];
        float x[D_IN];
        x[0] = hv[0]; x[1] = hv[1]; x[2] = hv[2];
        x[3] = hv[0]; x[4] = hv[1]; x[5] = hv[2];
        x[6] = hv[0]; x[7] = hv[1]; x[8] = hv[2];
        x[9]  = nf[r * 12 + 0];
        x[10] = nf[r * 12 + 1];
        x[11] = nf[r * 12 + 2];
        x[12] = wp[r * 3 + 0] - hv[3];
        x[13] = wp[r * 3 + 1] - hv[4];
        x[14] = wp[r * 3 + 2] - hv[5];
        x[15] = mp[r * 2 + 0] - hv[6];
        x[16] = mp[r * 2 + 1] - hv[7];
        float mu = 0.f;
#pragma unroll
        for (int k = 0; k < D_IN; k++) mu += x[k];
        mu *= (1.0f / D_IN);
        float var = 0.f;
#pragma unroll
        for (int k = 0; k < D_IN; k++) { float d = x[k] - mu; var += d * d; }
        var *= (1.0f / D_IN);
        float inv = rsqrtf(var + LN_EPS);
#pragma unroll
        for (int k = 0; k < D_IN; k++)
            g_x[t * D_IN + k] = (x[k] - mu) * inv * ln0s[k] + ln0b[k];
    }
}

// -------- MLP: 60 blocks x 128 threads, one row per block --------
__global__ void k_mlp(const float* __restrict__ w1, const float* __restrict__ b1,
                      const float* __restrict__ w2, const float* __restrict__ b2,
                      const float* __restrict__ w3, const float* __restrict__ b3,
                      const float* __restrict__ lnfs, const float* __restrict__ lnfb) {
    int row = blockIdx.x;
    int j = threadIdx.x;  // 0..127
    __shared__ float sx[D_IN];
    __shared__ float h1[D_H];
    __shared__ float h2[D_H];
    __shared__ float red[D_H];
    if (j < D_IN) sx[j] = g_x[row * D_IN + j];
    __syncthreads();
    float a = b1[j];
#pragma unroll
    for (int k = 0; k < D_IN; k++) a += sx[k] * w1[k * D_H + j];
    h1[j] = fmaxf(a, 0.f);
    __syncthreads();
    a = b2[j];
#pragma unroll 8
    for (int k = 0; k < D_H; k++) a += h1[k] * w2[k * D_H + j];
    h2[j] = fmaxf(a, 0.f);
    __syncthreads();
    a = b3[j];
#pragma unroll 8
    for (int k = 0; k < D_H; k++) a += h2[k] * w3[k * D_H + j];
    // layernorm over 128
    float val = a;
    red[j] = val;
    __syncthreads();
    for (int s = 64; s > 0; s >>= 1) {
        if (j < s) red[j] += red[j + s];
        __syncthreads();
    }
    float mu = red[0] * (1.0f / D_H);
    __syncthreads();
    float d = val - mu;
    red[j] = d * d;
    __syncthreads();
    for (int s = 64; s > 0; s >>= 1) {
        if (j < s) red[j] += red[j + s];
        __syncthreads();
    }
    float var = red[0] * (1.0f / D_H);
    float out = d * rsqrtf(var + LN_EPS) * lnfs[j] + lnfb[j];
    g_h[row * D_H + j] = out;
}

// -------- SM streaming copy (evict-first hints; half of the output) --------
__global__ void k_copy(float4* __restrict__ dst, const float4* __restrict__ src, int n4) {
    int i = blockIdx.x * blockDim.x + threadIdx.x;
    int stride = gridDim.x * blockDim.x;
    for (; i < n4; i += stride) {
        float4 v = __ldcs(&src[i]);   // streaming load: evict-first in L2
        __stcs(&dst[i], v);           // streaming store
    }
}

// -------- scatter-add after join; tail resets scratch for next graph replay --------
__global__ void k_scatter(float* __restrict__ out, const int* __restrict__ rip) {
    int row = blockIdx.x;
    int j = threadIdx.x;
    long long r = (long long)rip[row];
    out[r * D_H + j] += g_h[row * D_H + j];
    // zero scratch state for the next replay (60*128 = 7680 threads)
    int gid = row * D_H + j;
    if (gid < 2048) g_hist1[gid] = 0;
    if (gid >= 2048 && gid < 4096) g_hist2[gid - 2048] = 0;
    if (gid >= 4096 && gid < 5120) g_hist3[gid - 4096] = 0;
    if (gid >= 5120 && gid < 5128) g_state[gid - 5120] = 0;
}

extern "C" void kernel_launch(void* const* d_in, const int* in_sizes, int n_in,
                              void* d_out, int out_size) {
    const float* nf   = (const float*)d_in[0];
    const float* wp   = (const float*)d_in[1];
    const float* mp   = (const float*)d_in[2];
    const float* lat  = (const float*)d_in[3];
    const int*   rip  = (const int*)  d_in[4];
    const float* ln0s = (const float*)d_in[5];
    const float* ln0b = (const float*)d_in[6];
    const float* w1   = (const float*)d_in[7];
    const float* b1   = (const float*)d_in[8];
    const float* w2   = (const float*)d_in[9];
    const float* b2   = (const float*)d_in[10];
    const float* w3   = (const float*)d_in[11];
    const float* b3   = (const float*)d_in[12];
    const float* lnfs = (const float*)d_in[13];
    const float* lnfb = (const float*)d_in[14];
    float* out = (float*)d_out;

    // one-time side-streams + events for the parallel copy branches
    static cudaStream_t s2 = nullptr, s3 = nullptr;
    static cudaEvent_t evFork = nullptr, evJoin2 = nullptr, evJoin3 = nullptr;
    if (!s2) {
        cudaStreamCreateWithFlags(&s2, cudaStreamNonBlocking);
        cudaStreamCreateWithFlags(&s3, cudaStreamNonBlocking);
        cudaEventCreateWithFlags(&evFork, cudaEventDisableTiming);
        cudaEventCreateWithFlags(&evJoin2, cudaEventDisableTiming);
        cudaEventCreateWithFlags(&evJoin3, cudaEventDisableTiming);
    }

    // split the 512MB output copy across CE (s2) and SM (s3) engine paths
    size_t total = (size_t)out_size;            // floats
    size_t half4 = (total / 4) / 2;             // float4 count for first half
    size_t halfF = half4 * 4;                   // floats in first half

    cudaEventRecord(evFork, 0);
    cudaStreamWaitEvent(s2, evFork, 0);
    cudaStreamWaitEvent(s3, evFork, 0);

    // branch B: copy engine, first half
    cudaMemcpyAsync(out, lat, halfF * sizeof(float),
                    cudaMemcpyDeviceToDevice, s2);
    // branch C: SM streaming copy, second half
    k_copy<<<2368, 256, 0, s3>>>((float4*)(out + halfF),
                                 (const float4*)(lat + halfF),
                                 (int)(total / 4 - half4));

    // main chain (branch A) — hidden under the copies
    k_keys_hist1<<<1024, 256>>>(nf);
    k_scan<<<1, 256>>>(1);
    k_hist2<<<512, 256>>>();
    k_scan<<<1, 256>>>(2);
    k_hist3<<<512, 256>>>();
    k_scan<<<1, 256>>>(3);
    k_sum<<<SUM_BLOCKS, 256>>>(nf, wp, mp);
    k_finalize<<<1, 64>>>(nf, wp, mp, rip, ln0s, ln0b);
    k_mlp<<<S_RIP, D_H>>>(w1, b1, w2, b2, w3, b3, lnfs, lnfb);

    // join: scatter-add needs both copies and the MLP result
    cudaEventRecord(evJoin2, s2);
    cudaEventRecord(evJoin3, s3);
    cudaStreamWaitEvent(0, evJoin2, 0);
    cudaStreamWaitEvent(0, evJoin3, 0);
    k_scatter<<<S_RIP, D_H>>>(out, rip);
}

// round 11
// speedup vs baseline: 1.0244x; 1.0244x over previous
#include <cuda_runtime.h>
#include <math.h>

#define N_NODES   1000000
#define K_TOP     10000
#define S_RIP     60
#define D_H       128
#define D_IN      17
#define LN_EPS    1e-5f
#define SUM_BLOCKS 512
#define TIED_CAP  4096

// -------- device scratch (no allocations allowed) --------
__device__ unsigned int g_keys[N_NODES];
__device__ unsigned int g_hist1[2048];
__device__ unsigned int g_hist2[2048];
__device__ unsigned int g_hist3[1024];
// state: [0]=b1 [1]=K1 [2]=b2 [3]=K2 [4]=T [5]=need [6]=tied_count
__device__ unsigned int g_state[8];
__device__ float        g_partials[SUM_BLOCKS * 8];
__device__ int          g_tied[TIED_CAP];
__device__ float        g_x[S_RIP * D_IN];
__device__ float        g_h[S_RIP * D_H];

// -------- pass 1: keys + level-1 histogram (bits [21:31]) --------
__global__ void k_keys_hist1(const float* __restrict__ nf) {
    __shared__ unsigned int sh[2048];
    for (int i = threadIdx.x; i < 2048; i += blockDim.x) sh[i] = 0;
    __syncthreads();
    int stride = gridDim.x * blockDim.x;
    const float4* nf4 = (const float4*)nf;   // row i starts at float 12*i -> float4 3*i
    for (int i = blockIdx.x * blockDim.x + threadIdx.x; i < N_NODES; i += stride) {
        float4 v = nf4[i * 3];               // v.x,v.y,v.z = velocity
        float s = v.x * v.x + v.y * v.y + v.z * v.z;
        unsigned int u = __float_as_uint(s); // s >= 0: uint order == float order
        g_keys[i] = u;
        atomicAdd(&sh[u >> 21], 1u);
    }
    __syncthreads();
    for (int i = threadIdx.x; i < 2048; i += blockDim.x)
        if (sh[i]) atomicAdd(&g_hist1[i], sh[i]);
}

// -------- level-2 histogram over candidate bucket (bits [10:21]) --------
__global__ void k_hist2() {
    __shared__ unsigned int sh[2048];
    for (int i = threadIdx.x; i < 2048; i += blockDim.x) sh[i] = 0;
    __syncthreads();
    unsigned int b1 = g_state[0];
    int stride = gridDim.x * blockDim.x;
    for (int i = blockIdx.x * blockDim.x + threadIdx.x; i < N_NODES; i += stride) {
        unsigned int u = g_keys[i];
        if ((u >> 21) == b1) atomicAdd(&sh[(u >> 10) & 0x7FFu], 1u);
    }
    __syncthreads();
    for (int i = threadIdx.x; i < 2048; i += blockDim.x)
        if (sh[i]) atomicAdd(&g_hist2[i], sh[i]);
}

// -------- level-3 histogram (bits [0:10]) --------
__global__ void k_hist3() {
    __shared__ unsigned int sh[1024];
    for (int i = threadIdx.x; i < 1024; i += blockDim.x) sh[i] = 0;
    __syncthreads();
    unsigned int prefix21 = (g_state[0] << 11) | g_state[2];
    int stride = gridDim.x * blockDim.x;
    for (int i = blockIdx.x * blockDim.x + threadIdx.x; i < N_NODES; i += stride) {
        unsigned int u = g_keys[i];
        if ((u >> 10) == prefix21) atomicAdd(&sh[u & 0x3FFu], 1u);
    }
    __syncthreads();
    for (int i = threadIdx.x; i < 1024; i += blockDim.x)
        if (sh[i]) atomicAdd(&g_hist3[i], sh[i]);
}

// -------- single-block scan: find bucket containing the K-th largest --------
__global__ void k_scan(int level) {
    __shared__ unsigned int csum[256];
    __shared__ unsigned int suf[256];
    const unsigned int* hist = (level == 1) ? g_hist1 : (level == 2) ? g_hist2 : g_hist3;
    int nbins = (level == 3) ? 1024 : 2048;
    unsigned int K = (level == 1) ? (unsigned int)K_TOP
                   : (level == 2) ? g_state[1] : g_state[3];
    int t = threadIdx.x;
    int chunk = nbins / 256;
    unsigned int s = 0;
    for (int b = t * chunk; b < (t + 1) * chunk; b++) s += hist[b];
    csum[t] = s;
    __syncthreads();
    if (t == 0) {
        unsigned int acc = 0;
        for (int c = 255; c >= 0; c--) { suf[c] = acc; acc += csum[c]; }
    }
    __syncthreads();
    // walk own chunk top-down; exactly one thread finds the bucket
    unsigned int cum = suf[t];
    for (int b = (t + 1) * chunk - 1; b >= t * chunk; b--) {
        unsigned int h = hist[b];
        if (cum < K && cum + h >= K) {
            unsigned int rem = K - cum;
            if (level == 1)      { g_state[0] = (unsigned int)b; g_state[1] = rem; }
            else if (level == 2) { g_state[2] = (unsigned int)b; g_state[3] = rem; }
            else {
                g_state[4] = (g_state[0] << 21) | (g_state[2] << 10) | (unsigned int)b;
                g_state[5] = rem;
            }
        }
        cum += h;
    }
}

// -------- reduction: sums over keys > T; collect ties at == T --------
__global__ void k_sum(const float* __restrict__ nf, const float* __restrict__ wp,
                      const float* __restrict__ mp) {
    unsigned int T = g_state[4];
    float acc[8];
#pragma unroll
    for (int c = 0; c < 8; c++) acc[c] = 0.f;
    int stride = gridDim.x * blockDim.x;
    for (int i = blockIdx.x * blockDim.x + threadIdx.x; i < N_NODES; i += stride) {
        unsigned int u = g_keys[i];
        if (u > T) {
            acc[0] += nf[i * 12 + 0];
            acc[1] += nf[i * 12 + 1];
            acc[2] += nf[i * 12 + 2];
            acc[3] += wp[i * 3 + 0];
            acc[4] += wp[i * 3 + 1];
            acc[5] += wp[i * 3 + 2];
            acc[6] += mp[i * 2 + 0];
            acc[7] += mp[i * 2 + 1];
        } else if (u == T) {
            int p = (int)atomicAdd(&g_state[6], 1u);
            if (p < TIED_CAP) g_tied[p] = i;
        }
    }
    __shared__ float red[256];
    for (int c = 0; c < 8; c++) {
        red[threadIdx.x] = acc[c];
        __syncthreads();
        for (int s = 128; s > 0; s >>= 1) {
            if (threadIdx.x < s) red[threadIdx.x] += red[threadIdx.x + s];
            __syncthreads();
        }
        if (threadIdx.x == 0) g_partials[blockIdx.x * 8 + c] = red[0];
        __syncthreads();
    }
}

// -------- finalize: reduce partials, ties (sorted by index), build x + LN0 --------
__global__ void k_finalize(const float* __restrict__ nf, const float* __restrict__ wp,
                           const float* __restrict__ mp, const int* __restrict__ rip,
                           const float* __restrict__ ln0s, const float* __restrict__ ln0b) {
    __shared__ float hv[8];
    int t = threadIdx.x;
    if (t < 8) {
        float a = 0.f;
        for (int b = 0; b < SUM_BLOCKS; b++) a += g_partials[b * 8 + t];
        hv[t] = a;
    }
    __syncthreads();
    if (t == 0) {
        int cnt = (int)g_state[6];
        if (cnt > TIED_CAP) cnt = TIED_CAP;
        int need = (int)g_state[5];
        // insertion sort ascending -> matches stable lowest-index tie-break
        for (int i = 1; i < cnt; i++) {
            int v = g_tied[i];
            int j = i - 1;
            while (j >= 0 && g_tied[j] > v) { g_tied[j + 1] = g_tied[j]; j--; }
            g_tied[j + 1] = v;
        }
        for (int i = 0; i < need && i < cnt; i++) {
            int idx = g_tied[i];
            hv[0] += nf[idx * 12 + 0];
            hv[1] += nf[idx * 12 + 1];
            hv[2] += nf[idx * 12 + 2];
            hv[3] += wp[idx * 3 + 0];
            hv[4] += wp[idx * 3 + 1];
            hv[5] += wp[idx * 3 + 2];
            hv[6] += mp[idx * 2 + 0];
            hv[7] += mp[idx * 2 + 1];
        }
    }
    __syncthreads();
    if (t < S_RIP) {
        int r = rip[t];
        float x[D_IN];
        x[0] = hv[0]; x[1] = hv[1]; x[2] = hv[2];
        x[3] = hv[0]; x[4] = hv[1]; x[5] = hv[2];
        x[6] = hv[0]; x[7] = hv[1]; x[8] = hv[2];
        x[9]  = nf[r * 12 + 0];
        x[10] = nf[r * 12 + 1];
        x[11] = nf[r * 12 + 2];
        x[12] = wp[r * 3 + 0] - hv[3];
        x[13] = wp[r * 3 + 1] - hv[4];
        x[14] = wp[r * 3 + 2] - hv[5];
        x[15] = mp[r * 2 + 0] - hv[6];
        x[16] = mp[r * 2 + 1] - hv[7];
        float mu = 0.f;
#pragma unroll
        for (int k = 0; k < D_IN; k++) mu += x[k];
        mu *= (1.0f / D_IN);
        float var = 0.f;
#pragma unroll
        for (int k = 0; k < D_IN; k++) { float d = x[k] - mu; var += d * d; }
        var *= (1.0f / D_IN);
        float inv = rsqrtf(var + LN_EPS);
#pragma unroll
        for (int k = 0; k < D_IN; k++)
            g_x[t * D_IN + k] = (x[k] - mu) * inv * ln0s[k] + ln0b[k];
    }
}

// -------- MLP: 60 blocks x 128 threads, one row per block --------
__global__ void k_mlp(const float* __restrict__ w1, const float* __restrict__ b1,
                      const float* __restrict__ w2, const float* __restrict__ b2,
                      const float* __restrict__ w3, const float* __restrict__ b3,
                      const float* __restrict__ lnfs, const float* __restrict__ lnfb) {
    int row = blockIdx.x;
    int j = threadIdx.x;  // 0..127
    __shared__ float sx[D_IN];
    __shared__ float h1[D_H];
    __shared__ float h2[D_H];
    __shared__ float red[D_H];
    if (j < D_IN) sx[j] = g_x[row * D_IN + j];
    __syncthreads();
    float a = b1[j];
#pragma unroll
    for (int k = 0; k < D_IN; k++) a += sx[k] * w1[k * D_H + j];
    h1[j] = fmaxf(a, 0.f);
    __syncthreads();
    a = b2[j];
#pragma unroll 8
    for (int k = 0; k < D_H; k++) a += h1[k] * w2[k * D_H + j];
    h2[j] = fmaxf(a, 0.f);
    __syncthreads();
    a = b3[j];
#pragma unroll 8
    for (int k = 0; k < D_H; k++) a += h2[k] * w3[k * D_H + j];
    // layernorm over 128
    float val = a;
    red[j] = val;
    __syncthreads();
    for (int s = 64; s > 0; s >>= 1) {
        if (j < s) red[j] += red[j + s];
        __syncthreads();
    }
    float mu = red[0] * (1.0f / D_H);
    __syncthreads();
    float d = val - mu;
    red[j] = d * d;
    __syncthreads();
    for (int s = 64; s > 0; s >>= 1) {
        if (j < s) red[j] += red[j + s];
        __syncthreads();
    }
    float var = red[0] * (1.0f / D_H);
    float out = d * rsqrtf(var + LN_EPS) * lnfs[j] + lnfb[j];
    g_h[row * D_H + j] = out;
}

// -------- SM copy with 256-bit (32B) vectors: LDG.E.256 / STG.E.256 --------
__global__ void k_copy256(double4* __restrict__ dst, const double4* __restrict__ src, int n) {
    int i = blockIdx.x * blockDim.x + threadIdx.x;
    int stride = gridDim.x * blockDim.x;
    for (; i < n; i += stride) {
        double4 v = src[i];
        dst[i] = v;
    }
}

// -------- scatter-add after join; tail resets scratch for next graph replay --------
__global__ void k_scatter(float* __restrict__ out, const int* __restrict__ rip) {
    int row = blockIdx.x;
    int j = threadIdx.x;
    long long r = (long long)rip[row];
    out[r * D_H + j] += g_h[row * D_H + j];
    // zero scratch state for the next replay (60*128 = 7680 threads)
    int gid = row * D_H + j;
    if (gid < 2048) g_hist1[gid] = 0;
    if (gid >= 2048 && gid < 4096) g_hist2[gid - 2048] = 0;
    if (gid >= 4096 && gid < 5120) g_hist3[gid - 4096] = 0;
    if (gid >= 5120 && gid < 5128) g_state[gid - 5120] = 0;
}

extern "C" void kernel_launch(void* const* d_in, const int* in_sizes, int n_in,
                              void* d_out, int out_size) {
    const float* nf   = (const float*)d_in[0];
    const float* wp   = (const float*)d_in[1];
    const float* mp   = (const float*)d_in[2];
    const float* lat  = (const float*)d_in[3];
    const int*   rip  = (const int*)  d_in[4];
    const float* ln0s = (const float*)d_in[5];
    const float* ln0b = (const float*)d_in[6];
    const float* w1   = (const float*)d_in[7];
    const float* b1   = (const float*)d_in[8];
    const float* w2   = (const float*)d_in[9];
    const float* b2   = (const float*)d_in[10];
    const float* w3   = (const float*)d_in[11];
    const float* b3   = (const float*)d_in[12];
    const float* lnfs = (const float*)d_in[13];
    const float* lnfb = (const float*)d_in[14];
    float* out = (float*)d_out;

    // one-time side-stream + events for the parallel copy branch
    static cudaStream_t s2 = nullptr;
    static cudaEvent_t evFork = nullptr, evJoin = nullptr;
    if (!s2) {
        cudaStreamCreateWithFlags(&s2, cudaStreamNonBlocking);
        cudaEventCreateWithFlags(&evFork, cudaEventDisableTiming);
        cudaEventCreateWithFlags(&evJoin, cudaEventDisableTiming);
    }

    // 256-bit element counts: out_size floats -> /8 double4 elements
    int n32 = out_size / 8;           // total double4 elements (out_size = 128M -> 16M)
    int n32A = (n32 * 3) / 5;         // 60% on side branch
    int n32B = n32 - n32A;            // 40% on main branch after the chain
    size_t offF = (size_t)n32A * 8;   // float offset of second part

    // fork: side branch copies 60% concurrently with the select/MLP chain
    cudaEventRecord(evFork, 0);
    cudaStreamWaitEvent(s2, evFork, 0);
    k_copy256<<<2368, 256, 0, s2>>>((double4*)out, (const double4*)lat, n32A);

    // main chain (branch A)
    k_keys_hist1<<<1024, 256>>>(nf);
    k_scan<<<1, 256>>>(1);
    k_hist2<<<512, 256>>>();
    k_scan<<<1, 256>>>(2);
    k_hist3<<<512, 256>>>();
    k_scan<<<1, 256>>>(3);
    k_sum<<<SUM_BLOCKS, 256>>>(nf, wp, mp);
    k_finalize<<<1, 64>>>(nf, wp, mp, rip, ln0s, ln0b);
    k_mlp<<<S_RIP, D_H>>>(w1, b1, w2, b2, w3, b3, lnfs, lnfb);

    // main branch copies the remaining 40% after the chain
    k_copy256<<<2368, 256>>>((double4*)(out + offF), (const double4*)(lat + offF), n32B);

    // join: scatter-add needs both copies and the MLP result
    cudaEventRecord(evJoin, s2);
    cudaStreamWaitEvent(0, evJoin, 0);
    k_scatter<<<S_RIP, D_H>>>(out, rip);
}

// round 12
// speedup vs baseline: 1.1082x; 1.0818x over previous
#include <cuda_runtime.h>
#include <math.h>

#define N_NODES   1000000
#define K_TOP     10000
#define S_RIP     60
#define D_H       128
#define D_IN      17
#define LN_EPS    1e-5f
#define SUM_BLOCKS 512
#define TIED_CAP  4096

// -------- device scratch (no allocations allowed) --------
__device__ unsigned int g_keys[N_NODES];
__device__ unsigned int g_hist1[2048];
__device__ unsigned int g_hist2[2048];
__device__ unsigned int g_hist3[1024];
// state: [0]=b1 [1]=K1 [2]=b2 [3]=K2 [4]=T [5]=need [6]=tied_count
__device__ unsigned int g_state[8];
__device__ float        g_partials[SUM_BLOCKS * 8];
__device__ int          g_tied[TIED_CAP];
__device__ float        g_x[S_RIP * D_IN];
__device__ float        g_h[S_RIP * D_H];

// -------- pass 1: keys + level-1 histogram (bits [21:31]) --------
__global__ void k_keys_hist1(const float* __restrict__ nf) {
    __shared__ unsigned int sh[2048];
    for (int i = threadIdx.x; i < 2048; i += blockDim.x) sh[i] = 0;
    __syncthreads();
    int stride = gridDim.x * blockDim.x;
    const float4* nf4 = (const float4*)nf;   // row i starts at float 12*i -> float4 3*i
    for (int i = blockIdx.x * blockDim.x + threadIdx.x; i < N_NODES; i += stride) {
        float4 v = nf4[i * 3];               // v.x,v.y,v.z = velocity
        float s = v.x * v.x + v.y * v.y + v.z * v.z;
        unsigned int u = __float_as_uint(s); // s >= 0: uint order == float order
        g_keys[i] = u;
        atomicAdd(&sh[u >> 21], 1u);
    }
    __syncthreads();
    for (int i = threadIdx.x; i < 2048; i += blockDim.x)
        if (sh[i]) atomicAdd(&g_hist1[i], sh[i]);
}

// -------- level-2 histogram over candidate bucket (bits [10:21]) --------
__global__ void k_hist2() {
    __shared__ unsigned int sh[2048];
    for (int i = threadIdx.x; i < 2048; i += blockDim.x) sh[i] = 0;
    __syncthreads();
    unsigned int b1 = g_state[0];
    int stride = gridDim.x * blockDim.x;
    for (int i = blockIdx.x * blockDim.x + threadIdx.x; i < N_NODES; i += stride) {
        unsigned int u = g_keys[i];
        if ((u >> 21) == b1) atomicAdd(&sh[(u >> 10) & 0x7FFu], 1u);
    }
    __syncthreads();
    for (int i = threadIdx.x; i < 2048; i += blockDim.x)
        if (sh[i]) atomicAdd(&g_hist2[i], sh[i]);
}

// -------- level-3 histogram (bits [0:10]) --------
__global__ void k_hist3() {
    __shared__ unsigned int sh[1024];
    for (int i = threadIdx.x; i < 1024; i += blockDim.x) sh[i] = 0;
    __syncthreads();
    unsigned int prefix21 = (g_state[0] << 11) | g_state[2];
    int stride = gridDim.x * blockDim.x;
    for (int i = blockIdx.x * blockDim.x + threadIdx.x; i < N_NODES; i += stride) {
        unsigned int u = g_keys[i];
        if ((u >> 10) == prefix21) atomicAdd(&sh[u & 0x3FFu], 1u);
    }
    __syncthreads();
    for (int i = threadIdx.x; i < 1024; i += blockDim.x)
        if (sh[i]) atomicAdd(&g_hist3[i], sh[i]);
}

// -------- single-block scan: find bucket containing the K-th largest --------
__global__ void k_scan(int level) {
    __shared__ unsigned int csum[256];
    __shared__ unsigned int suf[256];
    const unsigned int* hist = (level == 1) ? g_hist1 : (level == 2) ? g_hist2 : g_hist3;
    int nbins = (level == 3) ? 1024 : 2048;
    unsigned int K = (level == 1) ? (unsigned int)K_TOP
                   : (level == 2) ? g_state[1] : g_state[3];
    int t = threadIdx.x;
    int chunk = nbins / 256;
    unsigned int s = 0;
    for (int b = t * chunk; b < (t + 1) * chunk; b++) s += hist[b];
    csum[t] = s;
    __syncthreads();
    if (t == 0) {
        unsigned int acc = 0;
        for (int c = 255; c >= 0; c--) { suf[c] = acc; acc += csum[c]; }
    }
    __syncthreads();
    // walk own chunk top-down; exactly one thread finds the bucket
    unsigned int cum = suf[t];
    for (int b = (t + 1) * chunk - 1; b >= t * chunk; b--) {
        unsigned int h = hist[b];
        if (cum < K && cum + h >= K) {
            unsigned int rem = K - cum;
            if (level == 1)      { g_state[0] = (unsigned int)b; g_state[1] = rem; }
            else if (level == 2) { g_state[2] = (unsigned int)b; g_state[3] = rem; }
            else {
                g_state[4] = (g_state[0] << 21) | (g_state[2] << 10) | (unsigned int)b;
                g_state[5] = rem;
            }
        }
        cum += h;
    }
}

// -------- reduction: sums over keys > T; collect ties at == T --------
__global__ void k_sum(const float* __restrict__ nf, const float* __restrict__ wp,
                      const float* __restrict__ mp) {
    unsigned int T = g_state[4];
    float acc[8];
#pragma unroll
    for (int c = 0; c < 8; c++) acc[c] = 0.f;
    int stride = gridDim.x * blockDim.x;
    for (int i = blockIdx.x * blockDim.x + threadIdx.x; i < N_NODES; i += stride) {
        unsigned int u = g_keys[i];
        if (u > T) {
            acc[0] += nf[i * 12 + 0];
            acc[1] += nf[i * 12 + 1];
            acc[2] += nf[i * 12 + 2];
            acc[3] += wp[i * 3 + 0];
            acc[4] += wp[i * 3 + 1];
            acc[5] += wp[i * 3 + 2];
            acc[6] += mp[i * 2 + 0];
            acc[7] += mp[i * 2 + 1];
        } else if (u == T) {
            int p = (int)atomicAdd(&g_state[6], 1u);
            if (p < TIED_CAP) g_tied[p] = i;
        }
    }
    __shared__ float red[256];
    for (int c = 0; c < 8; c++) {
        red[threadIdx.x] = acc[c];
        __syncthreads();
        for (int s = 128; s > 0; s >>= 1) {
            if (threadIdx.x < s) red[threadIdx.x] += red[threadIdx.x + s];
            __syncthreads();
        }
        if (threadIdx.x == 0) g_partials[blockIdx.x * 8 + c] = red[0];
        __syncthreads();
    }
}

// -------- finalize: reduce partials, ties (sorted by index), build x + LN0 --------
__global__ void k_finalize(const float* __restrict__ nf, const float* __restrict__ wp,
                           const float* __restrict__ mp, const int* __restrict__ rip,
                           const float* __restrict__ ln0s, const float* __restrict__ ln0b) {
    __shared__ float hv[8];
    int t = threadIdx.x;
    if (t < 8) {
        float a = 0.f;
        for (int b = 0; b < SUM_BLOCKS; b++) a += g_partials[b * 8 + t];
        hv[t] = a;
    }
    __syncthreads();
    if (t == 0) {
        int cnt = (int)g_state[6];
        if (cnt > TIED_CAP) cnt = TIED_CAP;
        int need = (int)g_state[5];
        // insertion sort ascending -> matches stable lowest-index tie-break
        for (int i = 1; i < cnt; i++) {
            int v = g_tied[i];
            int j = i - 1;
            while (j >= 0 && g_tied[j] > v) { g_tied[j + 1] = g_tied[j]; j--; }
            g_tied[j + 1] = v;
        }
        for (int i = 0; i < need && i < cnt; i++) {
            int idx = g_tied[i];
            hv[0] += nf[idx * 12 + 0];
            hv[1] += nf[idx * 12 + 1];
            hv[2] += nf[idx * 12 + 2];
            hv[3] += wp[idx * 3 + 0];
            hv[4] += wp[idx * 3 + 1];
            hv[5] += wp[idx * 3 + 2];
            hv[6] += mp[idx * 2 + 0];
            hv[7] += mp[idx * 2 + 1];
        }
    }
    __syncthreads();
    if (t < S_RIP) {
        int r = rip[t];
        float x[D_IN];
        x[0] = hv[0]; x[1] = hv[1]; x[2] = hv[2];
        x[3] = hv[0]; x[4] = hv[1]; x[5] = hv[2];
        x[6] = hv[0]; x[7] = hv[1]; x[8] = hv[2];
        x[9]  = nf[r * 12 + 0];
        x[10] = nf[r * 12 + 1];
        x[11] = nf[r * 12 + 2];
        x[12] = wp[r * 3 + 0] - hv[3];
        x[13] = wp[r * 3 + 1] - hv[4];
        x[14] = wp[r * 3 + 2] - hv[5];
        x[15] = mp[r * 2 + 0] - hv[6];
        x[16] = mp[r * 2 + 1] - hv[7];
        float mu = 0.f;
#pragma unroll
        for (int k = 0; k < D_IN; k++) mu += x[k];
        mu *= (1.0f / D_IN);
        float var = 0.f;
#pragma unroll
        for (int k = 0; k < D_IN; k++) { float d = x[k] - mu; var += d * d; }
        var *= (1.0f / D_IN);
        float inv = rsqrtf(var + LN_EPS);
#pragma unroll
        for (int k = 0; k < D_IN; k++)
            g_x[t * D_IN + k] = (x[k] - mu) * inv * ln0s[k] + ln0b[k];
    }
}

// -------- MLP: 60 blocks x 128 threads, one row per block --------
__global__ void k_mlp(const float* __restrict__ w1, const float* __restrict__ b1,
                      const float* __restrict__ w2, const float* __restrict__ b2,
                      const float* __restrict__ w3, const float* __restrict__ b3,
                      const float* __restrict__ lnfs, const float* __restrict__ lnfb) {
    int row = blockIdx.x;
    int j = threadIdx.x;  // 0..127
    __shared__ float sx[D_IN];
    __shared__ float h1[D_H];
    __shared__ float h2[D_H];
    __shared__ float red[D_H];
    if (j < D_IN) sx[j] = g_x[row * D_IN + j];
    __syncthreads();
    float a = b1[j];
#pragma unroll
    for (int k = 0; k < D_IN; k++) a += sx[k] * w1[k * D_H + j];
    h1[j] = fmaxf(a, 0.f);
    __syncthreads();
    a = b2[j];
#pragma unroll 8
    for (int k = 0; k < D_H; k++) a += h1[k] * w2[k * D_H + j];
    h2[j] = fmaxf(a, 0.f);
    __syncthreads();
    a = b3[j];
#pragma unroll 8
    for (int k = 0; k < D_H; k++) a += h2[k] * w3[k * D_H + j];
    // layernorm over 128
    float val = a;
    red[j] = val;
    __syncthreads();
    for (int s = 64; s > 0; s >>= 1) {
        if (j < s) red[j] += red[j + s];
        __syncthreads();
    }
    float mu = red[0] * (1.0f / D_H);
    __syncthreads();
    float d = val - mu;
    red[j] = d * d;
    __syncthreads();
    for (int s = 64; s > 0; s >>= 1) {
        if (j < s) red[j] += red[j + s];
        __syncthreads();
    }
    float var = red[0] * (1.0f / D_H);
    float out = d * rsqrtf(var + LN_EPS) * lnfs[j] + lnfb[j];
    g_h[row * D_H + j] = out;
}

// -------- bulk copy: SM float4 streaming (evict-first, protects L2 for chain) --------
__global__ void k_copy(float4* __restrict__ dst, const float4* __restrict__ src, int n4) {
    int i = blockIdx.x * blockDim.x + threadIdx.x;
    int stride = gridDim.x * blockDim.x;
#pragma unroll 4
    for (; i < n4; i += stride) {
        float4 v = __ldcs(&src[i]);   // evict-first: don't pollute L2
        __stcs(&dst[i], v);
    }
}

// -------- scatter-add after join; tail resets scratch for next graph replay --------
__global__ void k_scatter(float* __restrict__ out, const int* __restrict__ rip) {
    int row = blockIdx.x;
    int j = threadIdx.x;
    long long r = (long long)rip[row];
    out[r * D_H + j] += g_h[row * D_H + j];
    // zero scratch state for the next replay (60*128 = 7680 threads)
    int gid = row * D_H + j;
    if (gid < 2048) g_hist1[gid] = 0;
    if (gid >= 2048 && gid < 4096) g_hist2[gid - 2048] = 0;
    if (gid >= 4096 && gid < 5120) g_hist3[gid - 4096] = 0;
    if (gid >= 5120 && gid < 5128) g_state[gid - 5120] = 0;
}

extern "C" void kernel_launch(void* const* d_in, const int* in_sizes, int n_in,
                              void* d_out, int out_size) {
    const float* nf   = (const float*)d_in[0];
    const float* wp   = (const float*)d_in[1];
    const float* mp   = (const float*)d_in[2];
    const float* lat  = (const float*)d_in[3];
    const int*   rip  = (const int*)  d_in[4];
    const float* ln0s = (const float*)d_in[5];
    const float* ln0b = (const float*)d_in[6];
    const float* w1   = (const float*)d_in[7];
    const float* b1   = (const float*)d_in[8];
    const float* w2   = (const float*)d_in[9];
    const float* b2   = (const float*)d_in[10];
    const float* w3   = (const float*)d_in[11];
    const float* b3   = (const float*)d_in[12];
    const float* lnfs = (const float*)d_in[13];
    const float* lnfb = (const float*)d_in[14];
    float* out = (float*)d_out;

    // one-time side-stream + events for the parallel copy branch
    static cudaStream_t s2 = nullptr;
    static cudaEvent_t evFork = nullptr, evJoin = nullptr;
    if (!s2) {
        cudaStreamCreateWithFlags(&s2, cudaStreamNonBlocking);
        cudaEventCreateWithFlags(&evFork, cudaEventDisableTiming);
        cudaEventCreateWithFlags(&evJoin, cudaEventDisableTiming);
    }

    // fork: streaming bulk copy runs concurrently with the select/MLP chain
    cudaEventRecord(evFork, 0);
    cudaStreamWaitEvent(s2, evFork, 0);
    k_copy<<<2368, 256, 0, s2>>>((float4*)out, (const float4*)lat, out_size / 4);

    // main chain (branch A) — hidden under the copy; re-reads stay L2-resident
    k_keys_hist1<<<1024, 256>>>(nf);
    k_scan<<<1, 256>>>(1);
    k_hist2<<<512, 256>>>();
    k_scan<<<1, 256>>>(2);
    k_hist3<<<512, 256>>>();
    k_scan<<<1, 256>>>(3);
    k_sum<<<SUM_BLOCKS, 256>>>(nf, wp, mp);
    k_finalize<<<1, 64>>>(nf, wp, mp, rip, ln0s, ln0b);
    k_mlp<<<S_RIP, D_H>>>(w1, b1, w2, b2, w3, b3, lnfs, lnfb);

    // join: scatter-add needs both the copy and the MLP result
    cudaEventRecord(evJoin, s2);
    cudaStreamWaitEvent(0, evJoin, 0);
    k_scatter<<<S_RIP, D_H>>>(out, rip);
}